// round 13
// baseline (speedup 1.0000x reference)
#include <cuda_runtime.h>
#include <cuda_bf16.h>
#include <cstdint>
#include <cstddef>

#define Bb 2048
#define Nn 200
#define Ee 128
#define ROWS (Bb * Nn)   // 409600

// ---------------------------------------------------------------------------
// Static device scratch (no cudaMalloc allowed)
// ---------------------------------------------------------------------------
__device__ float g_K4 [(size_t)ROWS * 128];  // staging row-major x @ Wk.T
__device__ float g_V4 [(size_t)ROWS * 128];  // staging row-major x @ Wv.T
__device__ float g_Kx [(size_t)ROWS * 128];  // staging row-major x @ WprjK.T
__device__ float g_Xq2[(size_t)ROWS * 128];  // x @ Wq[:,128:256].T ("last" q contrib)
__device__ float g_Xq3[(size_t)ROWS * 128];  // x @ Wq[:,256:384].T ("first" q contrib)
__device__ float g_KT [(size_t)Bb * 128 * Nn];  // transposed (b, c, pos)
__device__ float g_VT [(size_t)Bb * 128 * Nn];
__device__ float g_XT [(size_t)Bb * 128 * Nn];
__device__ float g_Wcat[128 * 640];
__device__ float g_WoT [128 * 128];
__device__ float g_qh  [Bb * 128];
__device__ float g_qlast0 [128];
__device__ float g_qfirst0[128];
__device__ unsigned int g_fk0[Nn];
__device__ unsigned int g_fk1[Nn];

// ---------------------------------------------------------------------------
// Threefry-2x32 (20 rounds) — bitwise identical to JAX
// ---------------------------------------------------------------------------
__device__ __forceinline__ unsigned int rotl32(unsigned int v, int r) {
    return (v << r) | (v >> (32 - r));
}

__device__ __forceinline__ void tf2x32(unsigned int k0, unsigned int k1,
                                       unsigned int x0, unsigned int x1,
                                       unsigned int& o0, unsigned int& o1) {
    unsigned int ks[3];
    ks[0] = k0; ks[1] = k1; ks[2] = k0 ^ k1 ^ 0x1BD11BDAu;
    x0 += ks[0]; x1 += ks[1];
    const int R1[4] = {13, 15, 26, 6};
    const int R2[4] = {17, 29, 16, 24};
#pragma unroll
    for (int g = 0; g < 5; g++) {
        const int* R = (g & 1) ? R2 : R1;
#pragma unroll
        for (int j = 0; j < 4; j++) {
            x0 += x1;
            x1 = rotl32(x1, R[j]);
            x1 ^= x0;
        }
        x0 += ks[(g + 1) % 3];
        x1 += ks[(g + 2) % 3] + (unsigned int)(g + 1);
    }
    o0 = x0; o1 = x1;
}

// ---------------------------------------------------------------------------
// XLA EmitFastTanh (f32)
// ---------------------------------------------------------------------------
__device__ __forceinline__ float fast_tanh(float x) {
    if (fabsf(x) < 0.0004f) return x;
    float xc = fminf(fmaxf(x, -9.0f), 9.0f);
    float x2 = xc * xc;
    float num = -2.76076847742355e-16f;
    num = num * x2 + 2.00018790482477e-13f;
    num = num * x2 + -8.60467152213735e-11f;
    num = num * x2 + 5.12229709037114e-08f;
    num = num * x2 + 1.48572235717979e-05f;
    num = num * x2 + 6.37261928875436e-04f;
    num = num * x2 + 4.89352455891786e-03f;
    num = num * xc;
    float den = 1.19825839466702e-06f;
    den = den * x2 + 1.18534705686654e-04f;
    den = den * x2 + 2.26843463243900e-03f;
    den = den * x2 + 4.89352518554385e-03f;
    return num / den;
}

// ---------------------------------------------------------------------------
// Kernel 1: build Wcat / WoT / init-q vectors / per-step folded keys
// ---------------------------------------------------------------------------
__global__ void prep_kernel(const float* __restrict__ Wk, const float* __restrict__ Wv,
                            const float* __restrict__ WprjK, const float* __restrict__ Wq,
                            const float* __restrict__ Wo, const float* __restrict__ initK,
                            const float* __restrict__ initV) {
    int tid = blockIdx.x * blockDim.x + threadIdx.x;
    int nthr = gridDim.x * blockDim.x;

    for (int idx = tid; idx < 128 * 640; idx += nthr) {
        int k = idx / 640, c = idx % 640;
        float v;
        if      (c < 128) v = Wk[c * 128 + k];
        else if (c < 256) v = Wv[(c - 128) * 128 + k];
        else if (c < 384) v = WprjK[(c - 256) * 128 + k];
        else if (c < 512) v = Wq[(size_t)(c - 384) * 384 + 128 + k];
        else              v = Wq[(size_t)(c - 512) * 384 + 256 + k];
        g_Wcat[idx] = v;
    }
    for (int idx = tid; idx < 128 * 128; idx += nthr) {
        int k = idx >> 7, e = idx & 127;
        g_WoT[idx] = Wo[e * 128 + k];
    }
    for (int o = tid; o < 128; o += nthr) {
        float a = 0.f, b = 0.f;
        for (int k = 0; k < 128; k++) {
            a += initK[k] * Wq[(size_t)o * 384 + 128 + k];
            b += initV[k] * Wq[(size_t)o * 384 + 256 + k];
        }
        g_qlast0[o] = a;
        g_qfirst0[o] = b;
    }
    for (int i = tid; i < Nn; i += nthr) {
        unsigned int o0, o1;
        tf2x32(0u, 42u, 0u, (unsigned int)i, o0, o1);
        g_fk0[i] = o0; g_fk1[i] = o1;
    }
}

// ---------------------------------------------------------------------------
// Kernel 2: big fused GEMM  C(409600,640) = x(409600,128) @ Wcat(128,640)
// ---------------------------------------------------------------------------
__global__ void __launch_bounds__(256) gemm_kernel(const float* __restrict__ A) {
    __shared__ float sA[128][33];
    __shared__ float sW[32][64];
    int bn = blockIdx.x, bm = blockIdx.y;
    int t = threadIdx.x;
    int tx = t & 15, ty = t >> 4;
    float acc[8][4];
#pragma unroll
    for (int i = 0; i < 8; i++)
#pragma unroll
        for (int j = 0; j < 4; j++) acc[i][j] = 0.f;

    int mbase = bm * 128;
    for (int kb = 0; kb < 128; kb += 32) {
#pragma unroll
        for (int rr = 0; rr < 4; rr++) {
            int r = (t >> 3) + rr * 32;
            int c4 = (t & 7) * 4;
            float4 v = *(const float4*)&A[(size_t)(mbase + r) * 128 + kb + c4];
            sA[r][c4 + 0] = v.x; sA[r][c4 + 1] = v.y;
            sA[r][c4 + 2] = v.z; sA[r][c4 + 3] = v.w;
        }
#pragma unroll
        for (int rr = 0; rr < 2; rr++) {
            int kr = (t >> 4) + rr * 16;
            int c4 = (t & 15) * 4;
            *(float4*)&sW[kr][c4] =
                *(const float4*)&g_Wcat[(size_t)(kb + kr) * 640 + bn * 64 + c4];
        }
        __syncthreads();
#pragma unroll
        for (int kk = 0; kk < 32; kk++) {
            float a_[8];
#pragma unroll
            for (int i = 0; i < 8; i++) a_[i] = sA[ty * 8 + i][kk];
            float4 wv = *(const float4*)&sW[kk][tx * 4];
#pragma unroll
            for (int i = 0; i < 8; i++) {
                acc[i][0] += a_[i] * wv.x;
                acc[i][1] += a_[i] * wv.y;
                acc[i][2] += a_[i] * wv.z;
                acc[i][3] += a_[i] * wv.w;
            }
        }
        __syncthreads();
    }
    int colg = bn * 64 + tx * 4;
    float* out = (colg < 128) ? g_K4 : (colg < 256) ? g_V4
               : (colg < 384) ? g_Kx : (colg < 512) ? g_Xq2 : g_Xq3;
    int col = colg & 127;
#pragma unroll
    for (int i = 0; i < 8; i++) {
        float4 v = make_float4(acc[i][0], acc[i][1], acc[i][2], acc[i][3]);
        *(float4*)&out[(size_t)(mbase + ty * 8 + i) * 128 + col] = v;
    }
}

// ---------------------------------------------------------------------------
// Kernel 2b: per-b transpose  (b,n,c) -> (b,c,n) for K4 / V4 / Kx
// ---------------------------------------------------------------------------
__global__ void transpose_kernel() {
    int z = blockIdx.z;
    int arr = z / Bb, b = z % Bb;
    const float* src = (arr == 0) ? g_K4 : (arr == 1) ? g_V4 : g_Kx;
    float*       dst = (arr == 0) ? g_KT : (arr == 1) ? g_VT : g_XT;
    __shared__ float tile[32][33];
    int n0 = blockIdx.x * 32, c0 = blockIdx.y * 32;
    int tx = threadIdx.x, ty = threadIdx.y;
#pragma unroll
    for (int r = 0; r < 4; r++) {
        int n = n0 + ty + 8 * r;
        if (n < Nn) tile[ty + 8 * r][tx] = src[(size_t)(b * Nn + n) * 128 + c0 + tx];
    }
    __syncthreads();
    int n = n0 + tx;
    if (n < Nn) {
#pragma unroll
        for (int r = 0; r < 4; r++) {
            int c = c0 + ty + 8 * r;
            dst[(size_t)b * (128 * Nn) + (size_t)c * Nn + n] = tile[tx][ty + 8 * r];
        }
    }
}

// ---------------------------------------------------------------------------
// Kernel 3: hinit = mean_n x[b,n,:] ; qh = hinit @ Wq[:,0:128].T
// ---------------------------------------------------------------------------
__global__ void hinit_qh_kernel(const float* __restrict__ x, const float* __restrict__ Wq) {
    int b = blockIdx.x, t = threadIdx.x;
    __shared__ float sh[128];
    const float* xb = x + (size_t)b * Nn * Ee;
    float s = 0.f;
    for (int n = 0; n < Nn; n++) s += xb[(size_t)n * Ee + t];
    sh[t] = s / 200.0f;
    __syncthreads();
    float acc = 0.f;
    const float* wrow = Wq + (size_t)t * 384;
    for (int k = 0; k < 128; k++) acc += sh[k] * wrow[k];
    g_qh[b * 128 + t] = acc;
}

// ---------------------------------------------------------------------------
// Kernel 4: persistent decode — 1 block/SM, 512 threads, K+V resident in
// 204.8KB smem. Per-step DRAM = X logit stream + one prefetched Xq2 row.
// 2 warps per head; compaction swaps smem columns (K/V) + global (X).
// ---------------------------------------------------------------------------
#define DEC_SMEM (2 * 128 * Nn * 4)   // K + V tiles = 204800 bytes

__global__ void __launch_bounds__(512, 1) decode_kernel(void* outp, int mode,
                                                        const unsigned int* __restrict__ clipb) {
    extern __shared__ float smemDyn[];
    float* sK = smemDyn;              // [c*200+p], c = h*16+d
    float* sV = smemDyn + 128 * Nn;

    int b = blockIdx.x, t = threadIdx.x;
    int lane = t & 31, w = t >> 5;     // 16 warps

    __shared__ float sQ[128], sQh[128], sF3[128], sQv[128], sCtx[128];
    __shared__ float sPartCtx[16 * 16];
    __shared__ float sPm[16], sPs[16], sWv[16], sWl[16], sWs[16];
    __shared__ int   sWi[16];
    __shared__ float sLogit[224];
    __shared__ int   sIdx[Nn];
    __shared__ int   sSelP, sCnt;
    __shared__ float sM, sLogp;

    unsigned int cbits = *clipb;
    float cf = __uint_as_float(cbits);
    float clipv = (cf > 1e-6f && cf < 1e6f) ? cf : (float)(int)cbits;
    const float NEGINF = __int_as_float(0xff800000);
    const float TINY = 1.17549435e-38f;

    size_t bOff = (size_t)b * (128 * Nn);
    float* XT = g_XT + bOff;

    // ---- one-time: load K/V tiles into smem, init bookkeeping
    {
        const float4* srcK = (const float4*)(g_KT + bOff);
        const float4* srcV = (const float4*)(g_VT + bOff);
        float4* dK = (float4*)sK;
        float4* dV = (float4*)sV;
        for (int idx = t; idx < (128 * Nn) / 4; idx += 512) {
            dK[idx] = srcK[idx];
            dV[idx] = srcV[idx];
        }
    }
    for (int n = t; n < Nn; n += 512) sIdx[n] = n;
    if (t < 128) sQh[t] = g_qh[b * 128 + t];
    if (t == 0) { sLogp = 0.f; sCnt = Nn; }
    __syncthreads();

    float v2 = 0.f;   // prefetched Xq2[last] element for t<128

    for (int i = 0; i < Nn; i++) {
        int C = sCnt;

        // ---- A: q = qh + lastContrib + firstContrib (order matches reference hoisting)
        if (t < 128) {
            float q;
            if (i == 0)      q = sQh[t] + g_qlast0[t] + g_qfirst0[t];
            else             q = sQh[t] + v2 + sF3[t];
            sQ[t] = q;
        }
        __syncthreads();   // (1)

        // ---- B: attention, warp-pair per head
        int h = w >> 1, half = w & 1;
        const float* Kh = sK + h * 16 * Nn;
        const float* Vh = sV + h * 16 * Nn;
        const float* qh16 = sQ + h * 16;

        float v[4];
        float m = NEGINF;
#pragma unroll
        for (int j = 0; j < 4; j++) {
            int p = half * 32 + lane + 64 * j;
            float val = NEGINF;
            if (p < C) {
                float acc = 0.f;
#pragma unroll
                for (int d = 0; d < 16; d++) acc += qh16[d] * Kh[d * Nn + p];
                val = acc * 0.25f;
            }
            v[j] = val;
            m = fmaxf(m, val);
        }
#pragma unroll
        for (int off = 16; off; off >>= 1)
            m = fmaxf(m, __shfl_xor_sync(0xffffffffu, m, off));
        if (lane == 0) sPm[w] = m;
        __syncthreads();   // (2)

        float m2 = fmaxf(sPm[w & ~1], sPm[w | 1]);
        float sp = 0.f;
#pragma unroll
        for (int j = 0; j < 4; j++) sp += expf(v[j] - m2);
#pragma unroll
        for (int off = 16; off; off >>= 1)
            sp += __shfl_xor_sync(0xffffffffu, sp, off);
        if (lane == 0) sPs[w] = sp;
        __syncthreads();   // (3)

        float sTot = sPs[w & ~1] + sPs[w | 1];
        {
            float acc[16];
#pragma unroll
            for (int d = 0; d < 16; d++) acc[d] = 0.f;
#pragma unroll
            for (int j = 0; j < 4; j++) {
                int p = half * 32 + lane + 64 * j;
                if (p < C) {
                    float att = expf(v[j] - m2) / sTot;
#pragma unroll
                    for (int d = 0; d < 16; d++) acc[d] += att * Vh[d * Nn + p];
                }
            }
#pragma unroll
            for (int d = 0; d < 16; d++) {
                float r = acc[d];
#pragma unroll
                for (int off = 16; off; off >>= 1)
                    r += __shfl_xor_sync(0xffffffffu, r, off);
                if (lane == 0) sPartCtx[w * 16 + d] = r;
            }
        }
        __syncthreads();   // (4)

        if (t < 128) {
            int h2 = t >> 4, d2 = t & 15;
            sCtx[t] = sPartCtx[(2 * h2) * 16 + d2] + sPartCtx[(2 * h2 + 1) * 16 + d2];
        }
        __syncthreads();   // (5)

        // ---- C: qv = ctx @ Wo.T
        if (t < 128) {
            float acc = 0.f;
            for (int k = 0; k < 128; k++) acc += sCtx[k] * g_WoT[k * 128 + t];
            sQv[t] = acc;
        }
        __syncthreads();   // (6)

        // ---- D: pointer logits + Gumbel (X streamed from global, compacted)
        float logit = NEGINF, val = NEGINF;
        if (t < C) {
            const float* Xp = XT + t;
            float acc = 0.f;
#pragma unroll 8
            for (int e2 = 0; e2 < 128; e2++) acc += sQv[e2] * Xp[(size_t)e2 * Nn];
            logit = clipv * fast_tanh(acc * 0.0078125f);
            int n_orig = sIdx[t];
            unsigned int o0, o1;
            tf2x32(g_fk0[i], g_fk1[i], 0u, (unsigned int)(b * Nn + n_orig), o0, o1);
            unsigned int bits = o0 ^ o1;
            float u01 = __uint_as_float((bits >> 9) | 0x3f800000u) - 1.0f;
            float r = fmaxf(TINY, u01 * (1.0f - TINY) + TINY);
            float g = -logf(-logf(r));
            val = logit + g;
        }
        if (t < 224) sLogit[t] = logit;

        // ---- E: argmax(val) + max(logit), warp partials
        {
            int idx = t;
            float ml = logit;
#pragma unroll
            for (int off = 16; off; off >>= 1) {
                float ov = __shfl_xor_sync(0xffffffffu, val, off);
                int   oi = __shfl_xor_sync(0xffffffffu, idx, off);
                float ol = __shfl_xor_sync(0xffffffffu, ml,  off);
                if (ov > val || (ov == val && oi < idx)) { val = ov; idx = oi; }
                ml = fmaxf(ml, ol);
            }
            if (lane == 0) { sWv[w] = val; sWi[w] = idx; sWl[w] = ml; }
        }
        __syncthreads();   // (7)

        if (t == 0) {
            float bv = sWv[0]; int bi = sWi[0]; float M = sWl[0];
#pragma unroll
            for (int q = 1; q < 16; q++) {
                float ov = sWv[q]; int oi = sWi[q];
                if (ov > bv || (ov == bv && oi < bi)) { bv = ov; bi = oi; }
                M = fmaxf(M, sWl[q]);
            }
            sSelP = bi; sM = M;
        }
        __syncthreads();   // (8)

        int selP = sSelP;
        int last = C - 1;

        // sum of exp(logit - M) partials
        {
            float eterm = (t < C) ? expf(logit - sM) : 0.f;
#pragma unroll
            for (int off = 16; off; off >>= 1)
                eterm += __shfl_xor_sync(0xffffffffu, eterm, off);
            if (lane == 0) sWs[w] = eterm;
        }

        // compaction: K/V in smem (t<256), X in global (256<=t<384)
        if (selP != last) {
            if (t < 128)            sK[t * Nn + selP] = sK[t * Nn + last];
            else if (t < 256)       { int c = t - 128; sV[c * Nn + selP] = sV[c * Nn + last]; }
            else if (t < 384)       { int c = t - 256; XT[(size_t)c * Nn + selP] = XT[(size_t)c * Nn + last]; }
        }

        // prefetch next step's Xq2 row (and Xq3 row at i==0) — overlaps DRAM latency
        int selN = sIdx[selP];
        if (t < 128) {
            v2 = g_Xq2[((size_t)(b * Nn + selN)) * 128 + t];
            if (i == 0) sF3[t] = g_Xq3[((size_t)(b * Nn + selN)) * 128 + t];
        }
        __syncthreads();   // (9)

        if (t == 0) {
            float sum = 0.f;
#pragma unroll
            for (int q = 0; q < 16; q++) sum += sWs[q];
            sLogp += sLogit[selP] - sM - logf(sum);
            sIdx[selP] = sIdx[last];
            sCnt = last;
            if (mode == 0)      ((float*)outp)[(size_t)b * Nn + i] = (float)selN;
            else if (mode == 1) ((int*)outp)[(size_t)b * Nn + i] = selN;
        }
        __syncthreads();   // (10)
    }

    if (t == 0) {
        if (mode == 0)      ((float*)outp)[(size_t)Bb * Nn + b] = sLogp;
        else if (mode == 2) ((float*)outp)[b] = sLogp;
    }
}

// ---------------------------------------------------------------------------
// Host entry
// ---------------------------------------------------------------------------
extern "C" void kernel_launch(void* const* d_in, const int* in_sizes, int n_in,
                              void* d_out, int out_size) {
    const float* x     = (const float*)d_in[0];
    const float* initK = (const float*)d_in[1];
    const float* initV = (const float*)d_in[2];
    const float* WprjK = (const float*)d_in[3];
    const float* Wq    = (const float*)d_in[4];
    const float* Wk    = (const float*)d_in[5];
    const float* Wv    = (const float*)d_in[6];
    const float* Wo    = (const float*)d_in[7];
    const unsigned int* clipb = (const unsigned int*)d_in[8];

    static int smem_set = 0;
    if (!smem_set) {
        cudaFuncSetAttribute(decode_kernel,
                             cudaFuncAttributeMaxDynamicSharedMemorySize, DEC_SMEM);
        smem_set = 1;
    }

    prep_kernel<<<64, 256>>>(Wk, Wv, WprjK, Wq, Wo, initK, initV);
    gemm_kernel<<<dim3(10, 3200), 256>>>(x);
    transpose_kernel<<<dim3(7, 4, 3 * Bb), dim3(32, 8)>>>();
    hinit_qh_kernel<<<Bb, 128>>>(x, Wq);

    int mode;
    if (out_size >= Bb * Nn + Bb) mode = 0;       // float: visited then logp
    else if (out_size == Bb)      mode = 2;       // float: logp only
    else                          mode = 1;       // int: visited only

    decode_kernel<<<Bb, 512, DEC_SMEM>>>(d_out, mode, clipb);
}

// round 14
// speedup vs baseline: 1.8733x; 1.8733x over previous
#include <cuda_runtime.h>
#include <cuda_bf16.h>
#include <cstdint>
#include <cstddef>

#define Bb 2048
#define Nn 200
#define Ee 128
#define ROWS (Bb * Nn)   // 409600

// ---------------------------------------------------------------------------
// Static device scratch (no cudaMalloc allowed)
// ---------------------------------------------------------------------------
__device__ float g_K4 [(size_t)ROWS * 128];  // staging row-major x @ Wk.T
__device__ float g_V4 [(size_t)ROWS * 128];  // staging row-major x @ Wv.T
__device__ float g_Kx [(size_t)ROWS * 128];  // staging row-major x @ WprjK.T
__device__ float g_Xq2[(size_t)ROWS * 128];  // x @ Wq[:,128:256].T ("last" q contrib)
__device__ float g_Xq3[(size_t)ROWS * 128];  // x @ Wq[:,256:384].T ("first" q contrib)
__device__ float g_KT [(size_t)Bb * 128 * Nn];  // transposed (b, c, pos)
__device__ float g_VT [(size_t)Bb * 128 * Nn];
__device__ float g_XT [(size_t)Bb * 128 * Nn];
__device__ float g_Wcat[128 * 640];
__device__ float g_WoT [128 * 128];
__device__ float g_qh  [Bb * 128];
__device__ float g_qlast0 [128];
__device__ float g_qfirst0[128];
__device__ unsigned int g_fk0[Nn];
__device__ unsigned int g_fk1[Nn];

// ---------------------------------------------------------------------------
// Threefry-2x32 (20 rounds) — bitwise identical to JAX
// ---------------------------------------------------------------------------
__device__ __forceinline__ unsigned int rotl32(unsigned int v, int r) {
    return (v << r) | (v >> (32 - r));
}

__device__ __forceinline__ void tf2x32(unsigned int k0, unsigned int k1,
                                       unsigned int x0, unsigned int x1,
                                       unsigned int& o0, unsigned int& o1) {
    unsigned int ks[3];
    ks[0] = k0; ks[1] = k1; ks[2] = k0 ^ k1 ^ 0x1BD11BDAu;
    x0 += ks[0]; x1 += ks[1];
    const int R1[4] = {13, 15, 26, 6};
    const int R2[4] = {17, 29, 16, 24};
#pragma unroll
    for (int g = 0; g < 5; g++) {
        const int* R = (g & 1) ? R2 : R1;
#pragma unroll
        for (int j = 0; j < 4; j++) {
            x0 += x1;
            x1 = rotl32(x1, R[j]);
            x1 ^= x0;
        }
        x0 += ks[(g + 1) % 3];
        x1 += ks[(g + 2) % 3] + (unsigned int)(g + 1);
    }
    o0 = x0; o1 = x1;
}

// ---------------------------------------------------------------------------
// XLA EmitFastTanh (f32)
// ---------------------------------------------------------------------------
__device__ __forceinline__ float fast_tanh(float x) {
    if (fabsf(x) < 0.0004f) return x;
    float xc = fminf(fmaxf(x, -9.0f), 9.0f);
    float x2 = xc * xc;
    float num = -2.76076847742355e-16f;
    num = num * x2 + 2.00018790482477e-13f;
    num = num * x2 + -8.60467152213735e-11f;
    num = num * x2 + 5.12229709037114e-08f;
    num = num * x2 + 1.48572235717979e-05f;
    num = num * x2 + 6.37261928875436e-04f;
    num = num * x2 + 4.89352455891786e-03f;
    num = num * xc;
    float den = 1.19825839466702e-06f;
    den = den * x2 + 1.18534705686654e-04f;
    den = den * x2 + 2.26843463243900e-03f;
    den = den * x2 + 4.89352518554385e-03f;
    return num / den;
}

// ---------------------------------------------------------------------------
// Kernel 1: build Wcat / WoT / init-q vectors / per-step folded keys
// ---------------------------------------------------------------------------
__global__ void prep_kernel(const float* __restrict__ Wk, const float* __restrict__ Wv,
                            const float* __restrict__ WprjK, const float* __restrict__ Wq,
                            const float* __restrict__ Wo, const float* __restrict__ initK,
                            const float* __restrict__ initV) {
    int tid = blockIdx.x * blockDim.x + threadIdx.x;
    int nthr = gridDim.x * blockDim.x;

    for (int idx = tid; idx < 128 * 640; idx += nthr) {
        int k = idx / 640, c = idx % 640;
        float v;
        if      (c < 128) v = Wk[c * 128 + k];
        else if (c < 256) v = Wv[(c - 128) * 128 + k];
        else if (c < 384) v = WprjK[(c - 256) * 128 + k];
        else if (c < 512) v = Wq[(size_t)(c - 384) * 384 + 128 + k];
        else              v = Wq[(size_t)(c - 512) * 384 + 256 + k];
        g_Wcat[idx] = v;
    }
    for (int idx = tid; idx < 128 * 128; idx += nthr) {
        int k = idx >> 7, e = idx & 127;
        g_WoT[idx] = Wo[e * 128 + k];
    }
    for (int o = tid; o < 128; o += nthr) {
        float a = 0.f, b = 0.f;
        for (int k = 0; k < 128; k++) {
            a += initK[k] * Wq[(size_t)o * 384 + 128 + k];
            b += initV[k] * Wq[(size_t)o * 384 + 256 + k];
        }
        g_qlast0[o] = a;
        g_qfirst0[o] = b;
    }
    for (int i = tid; i < Nn; i += nthr) {
        unsigned int o0, o1;
        tf2x32(0u, 42u, 0u, (unsigned int)i, o0, o1);
        g_fk0[i] = o0; g_fk1[i] = o1;
    }
}

// ---------------------------------------------------------------------------
// Kernel 2: big fused GEMM  C(409600,640) = x(409600,128) @ Wcat(128,640)
// ---------------------------------------------------------------------------
__global__ void __launch_bounds__(256) gemm_kernel(const float* __restrict__ A) {
    __shared__ float sA[128][33];
    __shared__ float sW[32][64];
    int bn = blockIdx.x, bm = blockIdx.y;
    int t = threadIdx.x;
    int tx = t & 15, ty = t >> 4;
    float acc[8][4];
#pragma unroll
    for (int i = 0; i < 8; i++)
#pragma unroll
        for (int j = 0; j < 4; j++) acc[i][j] = 0.f;

    int mbase = bm * 128;
    for (int kb = 0; kb < 128; kb += 32) {
#pragma unroll
        for (int rr = 0; rr < 4; rr++) {
            int r = (t >> 3) + rr * 32;
            int c4 = (t & 7) * 4;
            float4 v = *(const float4*)&A[(size_t)(mbase + r) * 128 + kb + c4];
            sA[r][c4 + 0] = v.x; sA[r][c4 + 1] = v.y;
            sA[r][c4 + 2] = v.z; sA[r][c4 + 3] = v.w;
        }
#pragma unroll
        for (int rr = 0; rr < 2; rr++) {
            int kr = (t >> 4) + rr * 16;
            int c4 = (t & 15) * 4;
            *(float4*)&sW[kr][c4] =
                *(const float4*)&g_Wcat[(size_t)(kb + kr) * 640 + bn * 64 + c4];
        }
        __syncthreads();
#pragma unroll
        for (int kk = 0; kk < 32; kk++) {
            float a_[8];
#pragma unroll
            for (int i = 0; i < 8; i++) a_[i] = sA[ty * 8 + i][kk];
            float4 wv = *(const float4*)&sW[kk][tx * 4];
#pragma unroll
            for (int i = 0; i < 8; i++) {
                acc[i][0] += a_[i] * wv.x;
                acc[i][1] += a_[i] * wv.y;
                acc[i][2] += a_[i] * wv.z;
                acc[i][3] += a_[i] * wv.w;
            }
        }
        __syncthreads();
    }
    int colg = bn * 64 + tx * 4;
    float* out = (colg < 128) ? g_K4 : (colg < 256) ? g_V4
               : (colg < 384) ? g_Kx : (colg < 512) ? g_Xq2 : g_Xq3;
    int col = colg & 127;
#pragma unroll
    for (int i = 0; i < 8; i++) {
        float4 v = make_float4(acc[i][0], acc[i][1], acc[i][2], acc[i][3]);
        *(float4*)&out[(size_t)(mbase + ty * 8 + i) * 128 + col] = v;
    }
}

// ---------------------------------------------------------------------------
// Kernel 2b: per-b transpose  (b,n,c) -> (b,c,n) for K4 / V4 / Kx
// ---------------------------------------------------------------------------
__global__ void transpose_kernel() {
    int z = blockIdx.z;
    int arr = z / Bb, b = z % Bb;
    const float* src = (arr == 0) ? g_K4 : (arr == 1) ? g_V4 : g_Kx;
    float*       dst = (arr == 0) ? g_KT : (arr == 1) ? g_VT : g_XT;
    __shared__ float tile[32][33];
    int n0 = blockIdx.x * 32, c0 = blockIdx.y * 32;
    int tx = threadIdx.x, ty = threadIdx.y;
#pragma unroll
    for (int r = 0; r < 4; r++) {
        int n = n0 + ty + 8 * r;
        if (n < Nn) tile[ty + 8 * r][tx] = src[(size_t)(b * Nn + n) * 128 + c0 + tx];
    }
    __syncthreads();
    int n = n0 + tx;
    if (n < Nn) {
#pragma unroll
        for (int r = 0; r < 4; r++) {
            int c = c0 + ty + 8 * r;
            dst[(size_t)b * (128 * Nn) + (size_t)c * Nn + n] = tile[tx][ty + 8 * r];
        }
    }
}

// ---------------------------------------------------------------------------
// Kernel 3: hinit = mean_n x[b,n,:] ; qh = hinit @ Wq[:,0:128].T
// ---------------------------------------------------------------------------
__global__ void hinit_qh_kernel(const float* __restrict__ x, const float* __restrict__ Wq) {
    int b = blockIdx.x, t = threadIdx.x;
    __shared__ float sh[128];
    const float* xb = x + (size_t)b * Nn * Ee;
    float s = 0.f;
    for (int n = 0; n < Nn; n++) s += xb[(size_t)n * Ee + t];
    sh[t] = s / 200.0f;
    __syncthreads();
    float acc = 0.f;
    const float* wrow = Wq + (size_t)t * 384;
    for (int k = 0; k < 128; k++) acc += sh[k] * wrow[k];
    g_qh[b * 128 + t] = acc;
}

// ---------------------------------------------------------------------------
// Kernel 4: persistent decode — one block per batch row, 256 threads,
// 4 blocks/SM. MUFU-lean: all expf/logf guarded by active count, e[] stored
// once. Xq2[last] row prefetched to hide DRAM latency.
// ---------------------------------------------------------------------------
__global__ void __launch_bounds__(256, 4) decode_kernel(void* outp, int mode,
                                                        const unsigned int* __restrict__ clipb) {
    int b = blockIdx.x, t = threadIdx.x;
    int lane = t & 31, w = t >> 5;

    __shared__ float sQ[128], sQh[128], sF3[128], sQv[128], sCtx[128];
    __shared__ float sLogit[256];
    __shared__ int   sIdx[Nn];
    __shared__ float sWv[8], sWl[8], sWs[8];
    __shared__ int   sWi[8];
    __shared__ int   sSelP, sCnt;
    __shared__ float sM, sLogp;

    unsigned int cbits = *clipb;
    float cf = __uint_as_float(cbits);
    float clipv = (cf > 1e-6f && cf < 1e6f) ? cf : (float)(int)cbits;
    const float NEGINF = __int_as_float(0xff800000);
    const float TINY = 1.17549435e-38f;

    size_t bOff = (size_t)b * (128 * Nn);
    float* KT = g_KT + bOff;
    float* VT = g_VT + bOff;
    float* XT = g_XT + bOff;

    for (int n = t; n < Nn; n += 256) sIdx[n] = n;
    if (t < 128) sQh[t] = g_qh[b * 128 + t];
    if (t == 0) { sLogp = 0.f; sCnt = Nn; }
    __syncthreads();

    float v2 = 0.f;   // prefetched Xq2[last] element (t < 128)

    for (int i = 0; i < Nn; i++) {
        int C = sCnt;
        int nch = (C + 31) >> 5;

        // ---- A: q = qh + lastContrib + firstContrib
        if (t < 128) {
            float q;
            if (i == 0) q = sQh[t] + g_qlast0[t] + g_qfirst0[t];
            else        q = sQh[t] + v2 + sF3[t];
            sQ[t] = q;
        }
        __syncthreads();   // (1)

        // ---- B: attention, warp = head. Chunk loops uniform-bounded by nch.
        {
            int h = w;
            const float* Kh = KT + (size_t)h * 16 * Nn;
            const float* Vh = VT + (size_t)h * 16 * Nn;
            const float* qh16 = sQ + h * 16;

            float e[7];
            float m = NEGINF;
#pragma unroll
            for (int j = 0; j < 7; j++) {
                float val = NEGINF;
                if (j < nch) {
                    int p = j * 32 + lane;
                    if (p < C) {
                        float acc = 0.f;
#pragma unroll
                        for (int d = 0; d < 16; d++) acc += qh16[d] * Kh[d * Nn + p];
                        val = acc * 0.25f;
                    }
                }
                e[j] = val;      // scores for now
                m = fmaxf(m, val);
            }
#pragma unroll
            for (int off = 16; off; off >>= 1)
                m = fmaxf(m, __shfl_xor_sync(0xffffffffu, m, off));

            float s = 0.f;
#pragma unroll
            for (int j = 0; j < 7; j++) {
                float ee = 0.f;
                if (j < nch) ee = expf(e[j] - m);   // inactive lanes: expf(-inf)=0
                e[j] = ee;
                s += ee;
            }
#pragma unroll
            for (int off = 16; off; off >>= 1)
                s += __shfl_xor_sync(0xffffffffu, s, off);

            float acc[16];
#pragma unroll
            for (int d = 0; d < 16; d++) acc[d] = 0.f;
#pragma unroll
            for (int j = 0; j < 7; j++) {
                if (j < nch) {
                    int p = j * 32 + lane;
                    if (p < C) {
                        float att = e[j] / s;
#pragma unroll
                        for (int d = 0; d < 16; d++) acc[d] += att * Vh[d * Nn + p];
                    }
                }
            }
#pragma unroll
            for (int d = 0; d < 16; d++) {
                float r = acc[d];
#pragma unroll
                for (int off = 16; off; off >>= 1)
                    r += __shfl_xor_sync(0xffffffffu, r, off);
                if (lane == 0) sCtx[h * 16 + d] = r;
            }
        }
        __syncthreads();   // (2)

        // ---- C: qv = ctx @ Wo.T
        if (t < 128) {
            float acc = 0.f;
            for (int k = 0; k < 128; k++) acc += sCtx[k] * g_WoT[k * 128 + t];
            sQv[t] = acc;
        }
        __syncthreads();   // (3)

        // ---- D: pointer logits + Gumbel (X transposed+compacted, coalesced)
        float logit = NEGINF, val = NEGINF;
        if (t < C) {
            const float* Xp = XT + t;
            float acc = 0.f;
#pragma unroll 16
            for (int e2 = 0; e2 < 128; e2++) acc += sQv[e2] * Xp[(size_t)e2 * Nn];
            logit = clipv * fast_tanh(acc * 0.0078125f);
            int n_orig = sIdx[t];
            unsigned int o0, o1;
            tf2x32(g_fk0[i], g_fk1[i], 0u, (unsigned int)(b * Nn + n_orig), o0, o1);
            unsigned int bits = o0 ^ o1;
            float u01 = __uint_as_float((bits >> 9) | 0x3f800000u) - 1.0f;
            float r = fmaxf(TINY, u01 * (1.0f - TINY) + TINY);
            float g = -logf(-logf(r));
            val = logit + g;
        }
        sLogit[t] = logit;

        // warp partial: argmax(val) + max(logit)
        {
            int idx = t;
            float ml = logit;
#pragma unroll
            for (int off = 16; off; off >>= 1) {
                float ov = __shfl_xor_sync(0xffffffffu, val, off);
                int   oi = __shfl_xor_sync(0xffffffffu, idx, off);
                float ol = __shfl_xor_sync(0xffffffffu, ml,  off);
                if (ov > val || (ov == val && oi < idx)) { val = ov; idx = oi; }
                ml = fmaxf(ml, ol);
            }
            if (lane == 0) { sWv[w] = val; sWi[w] = idx; sWl[w] = ml; }
        }
        __syncthreads();   // (4)

        if (t == 0) {
            float bv = sWv[0]; int bi = sWi[0]; float M = sWl[0];
#pragma unroll
            for (int q = 1; q < 8; q++) {
                float ov = sWv[q]; int oi = sWi[q];
                if (ov > bv || (ov == bv && oi < bi)) { bv = ov; bi = oi; }
                M = fmaxf(M, sWl[q]);
            }
            sSelP = bi; sM = M;
        }
        __syncthreads();   // (5)

        int selP = sSelP;
        int last = C - 1;

        // sum of exp(logit - M): guarded by t < C
        {
            float eterm = (t < C) ? expf(logit - sM) : 0.f;
#pragma unroll
            for (int off = 16; off; off >>= 1)
                eterm += __shfl_xor_sync(0xffffffffu, eterm, off);
            if (lane == 0) sWs[w] = eterm;
        }

        // compaction: swap last active column into selP slot (K/V/X in global)
        if (selP != last) {
            for (int c = t; c < 384; c += 256) {
                float* arrp = (c < 128) ? KT : (c < 256) ? VT : XT;
                int cc = c & 127;
                arrp[(size_t)cc * Nn + selP] = arrp[(size_t)cc * Nn + last];
            }
        }

        // prefetch next step's Xq2 row (and Xq3 at i==0) — hides DRAM latency
        int selN = sIdx[selP];
        if (t < 128) {
            v2 = g_Xq2[((size_t)(b * Nn + selN)) * 128 + t];
            if (i == 0) sF3[t] = g_Xq3[((size_t)(b * Nn + selN)) * 128 + t];
        }
        __syncthreads();   // (6)

        if (t == 0) {
            float sum = 0.f;
#pragma unroll
            for (int q = 0; q < 8; q++) sum += sWs[q];
            sLogp += sLogit[selP] - sM - logf(sum);
            sIdx[selP] = sIdx[last];
            sCnt = last;
            if (mode == 0)      ((float*)outp)[(size_t)b * Nn + i] = (float)selN;
            else if (mode == 1) ((int*)outp)[(size_t)b * Nn + i] = selN;
        }
        __syncthreads();   // (7)
    }

    if (t == 0) {
        if (mode == 0)      ((float*)outp)[(size_t)Bb * Nn + b] = sLogp;
        else if (mode == 2) ((float*)outp)[b] = sLogp;
    }
}

// ---------------------------------------------------------------------------
// Host entry
// ---------------------------------------------------------------------------
extern "C" void kernel_launch(void* const* d_in, const int* in_sizes, int n_in,
                              void* d_out, int out_size) {
    const float* x     = (const float*)d_in[0];
    const float* initK = (const float*)d_in[1];
    const float* initV = (const float*)d_in[2];
    const float* WprjK = (const float*)d_in[3];
    const float* Wq    = (const float*)d_in[4];
    const float* Wk    = (const float*)d_in[5];
    const float* Wv    = (const float*)d_in[6];
    const float* Wo    = (const float*)d_in[7];
    const unsigned int* clipb = (const unsigned int*)d_in[8];

    prep_kernel<<<64, 256>>>(Wk, Wv, WprjK, Wq, Wo, initK, initV);
    gemm_kernel<<<dim3(10, 3200), 256>>>(x);
    transpose_kernel<<<dim3(7, 4, 3 * Bb), dim3(32, 8)>>>();
    hinit_qh_kernel<<<Bb, 128>>>(x, Wq);

    int mode;
    if (out_size >= Bb * Nn + Bb) mode = 0;       // float: visited then logp
    else if (out_size == Bb)      mode = 2;       // float: logp only
    else                          mode = 1;       // int: visited only

    decode_kernel<<<Bb, 256>>>(d_out, mode, clipb);
}